// round 16
// baseline (speedup 1.0000x reference)
#include <cuda_runtime.h>
#include <cuda_fp16.h>
#include <cstdint>
#include <math.h>

// Problem constants
#define BQ      4
#define NT      4096
#define CC      768
#define NHEADS  12
#define NPTS    4
#define HDIM    64
#define HIDDEN  3072
#define MROWS   (BQ*NT)          // 16384
#define SCALE_ATTN 0.125f        // 64^-0.5
#define QKVW    (3*CC)           // 2304
#define QX      2560             // qkv + 96 offset cols, padded to 256
#define NOFF    96

// ---------------- scratch (device globals; no cudaMalloc allowed) ----------
__device__ __half g_h[(size_t)MROWS * CC];          // ln out (fp16 GEMM A)
__device__ float  g_qkvx[(size_t)MROWS * QX];       // qkv + offsets fused (fp32)
__device__ __half g_attn[(size_t)MROWS * CC];       // attention output (fp16)
__device__ __half g_mlp[(size_t)MROWS * HIDDEN];    // gelu(fc1) (fp16)
// fp16 weight copies (prepared once per launch)
__device__ __half g_wqkvx[(size_t)QX * CC];         // qkv_w ++ Weff ++ zero pad
__device__ float  g_biasx[QX];                      // qkv_b ++ beff ++ 0
__device__ __half g_wproj[(size_t)CC * CC];
__device__ __half g_wfc1[(size_t)HIDDEN * CC];
__device__ __half g_wfc2[(size_t)CC * HIDDEN];

// ---------------- weight prep: all four fp32->fp16 conversions in one ------
#define WN0 (QKVW*CC/4)      // 442368
#define WN1 (CC*CC/4)        // 147456
#define WN2 (HIDDEN*CC/4)    // 589824
#define WN3 (CC*HIDDEN/4)    // 589824
#define WNT (WN0+WN1+WN2+WN3)

__global__ __launch_bounds__(256) void wconv_all_kernel(
    const float* __restrict__ s0, __half* __restrict__ d0,
    const float* __restrict__ s1, __half* __restrict__ d1,
    const float* __restrict__ s2, __half* __restrict__ d2,
    const float* __restrict__ s3, __half* __restrict__ d3)
{
    int i = blockIdx.x * 256 + threadIdx.x;
    if (i >= WNT) return;
    const float* s; __half* d; int j = i;
    if (j < WN0)            { s = s0; d = d0; }
    else if ((j -= WN0) < WN1) { s = s1; d = d1; }
    else if ((j -= WN1) < WN2) { s = s2; d = d2; }
    else                    { j -= WN2; s = s3; d = d3; }
    float4 v = ((const float4*)s)[j];
    __half2 h0 = __floats2half2_rn(v.x, v.y);
    __half2 h1 = __floats2half2_rn(v.z, v.w);
    ((uint2*)d)[j] = make_uint2(*(uint32_t*)&h0, *(uint32_t*)&h1);
}

// Weff[n][j] = sum_k off_w[n][k] * qkv_w[k][j]  (q rows of qkv_w), n<96
__global__ __launch_bounds__(256) void wcompose_kernel(
    const float* __restrict__ qkv_w, const float* __restrict__ off_w,
    __half* __restrict__ wqkvx)
{
    int n = blockIdx.x;
    int j = blockIdx.y * 256 + threadIdx.x;
    float s = 0.f;
    for (int k = 0; k < CC; k++)
        s = fmaf(__ldg(&off_w[n * CC + k]), qkv_w[(size_t)k * CC + j], s);
    wqkvx[(size_t)(QKVW + n) * CC + j] = __float2half_rn(s);
}

// bias vector [QX] and zero-pad rows 2400..QX-1 of wqkvx
__global__ __launch_bounds__(256) void biasprep_kernel(
    const float* __restrict__ qkv_b, const float* __restrict__ off_w,
    const float* __restrict__ off_b, float* __restrict__ biasx,
    __half* __restrict__ wqkvx)
{
    int i = blockIdx.x * 256 + threadIdx.x;
    if (i < QX) {
        if (i < QKVW) biasx[i] = qkv_b[i];
        else if (i < QKVW + NOFF) {
            int n = i - QKVW;
            float s = off_b[n];
            for (int k = 0; k < CC; k++) s = fmaf(off_w[n * CC + k], qkv_b[k], s);
            biasx[i] = s;
        } else biasx[i] = 0.f;
    }
    for (int z = blockIdx.x * 256 + threadIdx.x; z < (QX - QKVW - NOFF) * CC;
         z += gridDim.x * 256)
        wqkvx[(size_t)(QKVW + NOFF) * CC + z] = __float2half_rn(0.f);
}

// ---------------- LayerNorm: warp-per-row, 8 rows/block ---------------------
__global__ __launch_bounds__(256) void layernorm_kernel(
    const float* __restrict__ x, const float* __restrict__ w,
    const float* __restrict__ b, __half* __restrict__ out)
{
    int warp = threadIdx.x >> 5, lane = threadIdx.x & 31;
    int row = blockIdx.x * 8 + warp;
    const float* xr = x + (size_t)row * CC;

    float4 v[6];
    float s = 0.f, sq = 0.f;
    #pragma unroll
    for (int i = 0; i < 6; i++) {
        v[i] = ((const float4*)xr)[lane + i * 32];
        s  += v[i].x + v[i].y + v[i].z + v[i].w;
        sq += v[i].x*v[i].x + v[i].y*v[i].y + v[i].z*v[i].z + v[i].w*v[i].w;
    }
    #pragma unroll
    for (int o = 16; o > 0; o >>= 1) {
        s  += __shfl_xor_sync(0xffffffffu, s,  o);
        sq += __shfl_xor_sync(0xffffffffu, sq, o);
    }
    float mean = s * (1.0f / CC);
    float var  = sq * (1.0f / CC) - mean * mean;
    float rstd = rsqrtf(var + 1e-5f);

    __half* orow = out + (size_t)row * CC;
    #pragma unroll
    for (int i = 0; i < 6; i++) {
        int i4 = lane + i * 32;
        float4 wv = ((const float4*)w)[i4];
        float4 bv = ((const float4*)b)[i4];
        float r0 = (v[i].x - mean) * rstd * wv.x + bv.x;
        float r1 = (v[i].y - mean) * rstd * wv.y + bv.y;
        float r2 = (v[i].z - mean) * rstd * wv.z + bv.z;
        float r3 = (v[i].w - mean) * rstd * wv.w + bv.w;
        __half2 h01 = __floats2half2_rn(r0, r1);
        __half2 h23 = __floats2half2_rn(r2, r3);
        ((uint2*)orow)[i4] = make_uint2(*(uint32_t*)&h01, *(uint32_t*)&h23);
    }
}

// ============================================================================
// FP16 mma.sync GEMM: C[M,N] = A[M,K] * W[N,K]^T + bias (+epilogue)
// Block tile 128x256x32, 256 threads, warp tile 64x64, mma.m16n8k16,
// 3-stage cp.async.  (R12 proven config — GEMM pipe saturated, do not touch.)
// EPI: 0 = bias, 1 = bias + exact GELU, 2 = bias + residual add
// ============================================================================
#define HSTR 40        // smem row stride in halves (32 + 8 pad)
#define STG_H 15360    // halves per stage: A 128*40 + B 256*40
#define HSM_BYTES (3 * STG_H * 2)   // 92160

__device__ __forceinline__ void cp_async16(void* smem_dst, const void* gmem_src) {
    uint32_t s = (uint32_t)__cvta_generic_to_shared(smem_dst);
    asm volatile("cp.async.cg.shared.global [%0], [%1], 16;\n" :: "r"(s), "l"(gmem_src));
}

template<int EPI, typename OutT>
__global__ __launch_bounds__(256) void hgemm_nt(
    const __half* __restrict__ A,           // [M, K], lda == K
    const __half* __restrict__ Bw,          // [N', K], K contiguous
    const float* __restrict__ bias,
    const float* __restrict__ Res, int ldr,
    OutT* __restrict__ C, int ldc,
    int K, int nvalid)
{
    extern __shared__ __half smh[];

    const int t = threadIdx.x;
    const int rowTile = blockIdx.y * 128;
    const int colTile = blockIdx.x * 256;

    const int warp = t >> 5, lane = t & 31;
    const int wm = (warp & 1) * 64;        // 2 warps along M
    const int wn = (warp >> 1) * 64;       // 4 warps along N
    const int g  = lane >> 2;              // 0..7
    const int t4 = lane & 3;               // 0..3

    float acc[4][8][4];
    #pragma unroll
    for (int i = 0; i < 4; i++)
        #pragma unroll
        for (int j = 0; j < 8; j++)
            #pragma unroll
            for (int r = 0; r < 4; r++) acc[i][j][r] = 0.f;

    const int NK = K / 32;

    auto load_tile = [&](int kt, int buf) {
        const int kk = kt * 32;
        __half* As = smh + buf * STG_H;
        __half* Bs = As + 128 * HSTR;
        #pragma unroll
        for (int i = 0; i < 2; i++) {
            int c = t + i * 256;
            int row = c >> 2, kc = (c & 3) * 8;
            cp_async16(&As[row * HSTR + kc],
                       A + (size_t)(rowTile + row) * K + kk + kc);
        }
        #pragma unroll
        for (int i = 0; i < 4; i++) {
            int c = t + i * 256;
            int row = c >> 2, kc = (c & 3) * 8;
            cp_async16(&Bs[row * HSTR + kc],
                       Bw + (size_t)(colTile + row) * K + kk + kc);
        }
        asm volatile("cp.async.commit_group;\n");
    };

    load_tile(0, 0);
    if (NK > 1) load_tile(1, 1);

    for (int kt = 0; kt < NK; kt++) {
        const int buf = kt % 3;
        if (kt + 1 < NK) asm volatile("cp.async.wait_group 1;\n");
        else             asm volatile("cp.async.wait_group 0;\n");
        __syncthreads();

        const __half* As = smh + buf * STG_H;
        const __half* Bs = As + 128 * HSTR;

        #pragma unroll
        for (int ks = 0; ks < 2; ks++) {
            const int k0 = ks * 16;
            uint32_t afr[4][4];
            #pragma unroll
            for (int i = 0; i < 4; i++) {
                int rr = wm + i * 16 + g;
                afr[i][0] = *(const uint32_t*)&As[(rr    ) * HSTR + k0 + 2 * t4];
                afr[i][1] = *(const uint32_t*)&As[(rr + 8) * HSTR + k0 + 2 * t4];
                afr[i][2] = *(const uint32_t*)&As[(rr    ) * HSTR + k0 + 2 * t4 + 8];
                afr[i][3] = *(const uint32_t*)&As[(rr + 8) * HSTR + k0 + 2 * t4 + 8];
            }
            uint32_t bfr[8][2];
            #pragma unroll
            for (int j = 0; j < 8; j++) {
                int cc = wn + j * 8 + g;
                bfr[j][0] = *(const uint32_t*)&Bs[cc * HSTR + k0 + 2 * t4];
                bfr[j][1] = *(const uint32_t*)&Bs[cc * HSTR + k0 + 2 * t4 + 8];
            }
            #pragma unroll
            for (int i = 0; i < 4; i++)
                #pragma unroll
                for (int j = 0; j < 8; j++) {
                    asm volatile(
                        "mma.sync.aligned.m16n8k16.row.col.f32.f16.f16.f32 "
                        "{%0,%1,%2,%3}, {%4,%5,%6,%7}, {%8,%9}, {%0,%1,%2,%3};\n"
                        : "+f"(acc[i][j][0]), "+f"(acc[i][j][1]),
                          "+f"(acc[i][j][2]), "+f"(acc[i][j][3])
                        : "r"(afr[i][0]), "r"(afr[i][1]), "r"(afr[i][2]), "r"(afr[i][3]),
                          "r"(bfr[j][0]), "r"(bfr[j][1]));
                }
        }

        if (kt + 2 < NK) load_tile(kt + 2, (kt + 2) % 3);
    }

    // epilogue: acc[i][j] -> rows {wm+i*16+g, +8}, cols {wn+j*8+2*t4, +1}
    #pragma unroll
    for (int i = 0; i < 4; i++) {
        #pragma unroll
        for (int half = 0; half < 2; half++) {
            int r = rowTile + wm + i * 16 + g + half * 8;
            OutT* crow = C + (size_t)r * ldc;
            const float* rrow = (EPI == 2) ? (Res + (size_t)r * ldr) : nullptr;
            #pragma unroll
            for (int j = 0; j < 8; j++) {
                int cg = colTile + wn + j * 8 + t4 * 2;
                if (cg >= nvalid) continue;
                float v0 = acc[i][j][half * 2 + 0] + bias[cg];
                float v1 = acc[i][j][half * 2 + 1] + bias[cg + 1];
                if (EPI == 1) {
                    v0 = 0.5f * v0 * (1.0f + erff(v0 * 0.70710678118654752f));
                    v1 = 0.5f * v1 * (1.0f + erff(v1 * 0.70710678118654752f));
                }
                if (EPI == 2) { v0 += rrow[cg]; v1 += rrow[cg + 1]; }
                if (sizeof(OutT) == 2) {
                    __half2 hv = __floats2half2_rn(v0, v1);
                    *(__half2*)((__half*)crow + cg) = hv;
                } else {
                    *(float2*)((float*)crow + cg) = make_float2(v0, v1);
                }
            }
        }
    }
}

// ---------------- deformable sampling + attention --------------------------
// 2 tokens per 384-thread block; 6 warps per token; warp = 2 heads
// (half-warp = 16 lanes x float4 = 64 channels per head).
__global__ __launch_bounds__(384) void attn_kernel(
    const float* __restrict__ qkvx,   // [M, QX] fp32 (qkv ++ offsets)
    const float* __restrict__ refp,   // [M, 2]
    __half* __restrict__ out,         // [M, 768] fp16
    const int* __restrict__ Hp, const int* __restrict__ Wp)
{
    int tok  = threadIdx.x / 192;     // 0/1
    int tid  = threadIdx.x % 192;
    int bn   = blockIdx.x * 2 + tok;
    int warp = tid >> 5;
    int lane = tid & 31;
    int hsel = lane >> 4;             // 0/1: which head in this warp
    int hlane = lane & 15;            // lane within head (owns 4 channels)
    int head = warp * 2 + hsel;
    int b = bn / NT;

    int H = *Hp, W = *Wp;
    float fW = (float)W, fH = (float)H;

    const float* rowq = qkvx + (size_t)bn * QX;
    float4 q = ((const float4*)(rowq + head * HDIM))[hlane];

    float ref0 = refp[(size_t)bn * 2 + 0];
    float ref1 = refp[(size_t)bn * 2 + 1];

    const float* offp = rowq + QKVW + head * (NPTS * 2);

    float dots[NPTS];
    float4 sv[NPTS];

    #pragma unroll
    for (int p = 0; p < NPTS; p++) {
        float o0 = offp[p * 2 + 0];
        float o1 = offp[p * 2 + 1];
        float gx = 2.0f * (ref0 + o0 / fW) - 1.0f;
        float gy = 2.0f * (ref1 + o1 / fH) - 1.0f;
        float x = ((gx + 1.0f) * fW - 1.0f) * 0.5f;
        float y = ((gy + 1.0f) * fH - 1.0f) * 0.5f;
        float x0f = floorf(x), y0f = floorf(y);
        float wx = x - x0f, wy = y - y0f;
        int x0 = (int)x0f, y0 = (int)y0f;

        float cw[4] = {(1.f - wx) * (1.f - wy), wx * (1.f - wy),
                       (1.f - wx) * wy,          wx * wy};
        int cx[4] = {x0, x0 + 1, x0,     x0 + 1};
        int cy[4] = {y0, y0,     y0 + 1, y0 + 1};

        float4 sk = make_float4(0.f, 0.f, 0.f, 0.f);
        float4 vv = make_float4(0.f, 0.f, 0.f, 0.f);
        #pragma unroll
        for (int c = 0; c < 4; c++) {
            int ix = cx[c], iy = cy[c];
            if (ix >= 0 && ix < W && iy >= 0 && iy < H) {
                const float* rowk = qkvx + (size_t)(b * NT + iy * W + ix) * QX
                                  + head * HDIM;
                float4 k4 = ((const float4*)(rowk + CC))[hlane];
                float4 v4 = ((const float4*)(rowk + 2 * CC))[hlane];
                float w = cw[c];
                sk.x = fmaf(w, k4.x, sk.x); sk.y = fmaf(w, k4.y, sk.y);
                sk.z = fmaf(w, k4.z, sk.z); sk.w = fmaf(w, k4.w, sk.w);
                vv.x = fmaf(w, v4.x, vv.x); vv.y = fmaf(w, v4.y, vv.y);
                vv.z = fmaf(w, v4.z, vv.z); vv.w = fmaf(w, v4.w, vv.w);
            }
        }
        sv[p] = vv;

        float dot = q.x * sk.x + q.y * sk.y + q.z * sk.z + q.w * sk.w;
        #pragma unroll
        for (int o = 8; o > 0; o >>= 1)
            dot += __shfl_xor_sync(0xffffffffu, dot, o);   // 16-lane reduce
        dots[p] = dot * SCALE_ATTN;
    }

    float mx = fmaxf(fmaxf(dots[0], dots[1]), fmaxf(dots[2], dots[3]));
    float e[NPTS], es = 0.f;
    #pragma unroll
    for (int p = 0; p < NPTS; p++) { e[p] = __expf(dots[p] - mx); es += e[p]; }
    float inv = 1.0f / es;

    float4 o4 = make_float4(0.f, 0.f, 0.f, 0.f);
    #pragma unroll
    for (int p = 0; p < NPTS; p++) {
        float a = e[p] * inv;
        o4.x = fmaf(a, sv[p].x, o4.x); o4.y = fmaf(a, sv[p].y, o4.y);
        o4.z = fmaf(a, sv[p].z, o4.z); o4.w = fmaf(a, sv[p].w, o4.w);
    }
    __half2 h01 = __floats2half2_rn(o4.x, o4.y);
    __half2 h23 = __floats2half2_rn(o4.z, o4.w);
    *(uint2*)(out + (size_t)bn * CC + head * HDIM + hlane * 4)
        = make_uint2(*(uint32_t*)&h01, *(uint32_t*)&h23);
}

// ---------------- launch ----------------------------------------------------
extern "C" void kernel_launch(void* const* d_in, const int* in_sizes, int n_in,
                              void* d_out, int out_size)
{
    const float* x      = (const float*)d_in[0];
    const float* refp   = (const float*)d_in[1];
    const float* n1w    = (const float*)d_in[2];
    const float* n1b    = (const float*)d_in[3];
    const float* qkv_w  = (const float*)d_in[4];
    const float* qkv_b  = (const float*)d_in[5];
    const float* off_w  = (const float*)d_in[6];
    const float* off_b  = (const float*)d_in[7];
    const float* proj_w = (const float*)d_in[8];
    const float* proj_b = (const float*)d_in[9];
    const float* n2w    = (const float*)d_in[10];
    const float* n2b    = (const float*)d_in[11];
    const float* fc1_w  = (const float*)d_in[12];
    const float* fc1_b  = (const float*)d_in[13];
    const float* fc2_w  = (const float*)d_in[14];
    const float* fc2_b  = (const float*)d_in[15];
    const int*   Hp     = (const int*)d_in[16];
    const int*   Wp     = (const int*)d_in[17];
    float* out = (float*)d_out;

    __half* h     = nullptr; cudaGetSymbolAddress((void**)&h,     g_h);
    float*  qkvx  = nullptr; cudaGetSymbolAddress((void**)&qkvx,  g_qkvx);
    __half* attn  = nullptr; cudaGetSymbolAddress((void**)&attn,  g_attn);
    __half* mlp   = nullptr; cudaGetSymbolAddress((void**)&mlp,   g_mlp);
    __half* wqkvx = nullptr; cudaGetSymbolAddress((void**)&wqkvx, g_wqkvx);
    float*  biasx = nullptr; cudaGetSymbolAddress((void**)&biasx, g_biasx);
    __half* wproj = nullptr; cudaGetSymbolAddress((void**)&wproj, g_wproj);
    __half* wfc1  = nullptr; cudaGetSymbolAddress((void**)&wfc1,  g_wfc1);
    __half* wfc2  = nullptr; cudaGetSymbolAddress((void**)&wfc2,  g_wfc2);

    static bool attr_done = false;
    if (!attr_done) {
        cudaFuncSetAttribute((const void*)hgemm_nt<0,float>,  cudaFuncAttributeMaxDynamicSharedMemorySize, HSM_BYTES);
        cudaFuncSetAttribute((const void*)hgemm_nt<1,__half>, cudaFuncAttributeMaxDynamicSharedMemorySize, HSM_BYTES);
        cudaFuncSetAttribute((const void*)hgemm_nt<2,float>,  cudaFuncAttributeMaxDynamicSharedMemorySize, HSM_BYTES);
        attr_done = true;
    }

    // 0) weight prep (merged conversions + compose + bias)
    wconv_all_kernel<<<(WNT + 255) / 256, 256>>>(qkv_w, wqkvx, proj_w, wproj,
                                                 fc1_w, wfc1, fc2_w, wfc2);
    { dim3 g(NOFF, CC / 256); wcompose_kernel<<<g, 256>>>(qkv_w, off_w, wqkvx); }
    biasprep_kernel<<<(QX + 255) / 256, 256>>>(qkv_b, off_w, off_b, biasx, wqkvx);

    // 1) ln1: x -> h (fp16)
    layernorm_kernel<<<MROWS / 8, 256>>>(x, n1w, n1b, h);

    // 2) qkvx = h @ [qkv_w;Weff]^T + bias : [16384, QX] fp32 (valid 2400)
    {
        dim3 grid(QX / 256, MROWS / 128);
        hgemm_nt<0,float><<<grid, 256, HSM_BYTES>>>(h, wqkvx, biasx,
                                                    nullptr, 0, qkvx, QX,
                                                    CC, QKVW + NOFF);
    }

    // 3) deformable sampling + attention -> attn [16384, 768] fp16
    attn_kernel<<<BQ * NT / 2, 384>>>(qkvx, refp, attn, Hp, Wp);

    // 4) x1 = x + attn @ proj_w^T + proj_b -> out (fp32)
    {
        dim3 grid(CC / 256, MROWS / 128);
        hgemm_nt<2,float><<<grid, 256, HSM_BYTES>>>(attn, wproj, proj_b,
                                                    x, CC, out, CC, CC, CC);
    }

    // 5) ln2: out -> h (fp16)
    layernorm_kernel<<<MROWS / 8, 256>>>(out, n2w, n2b, h);

    // 6) m = gelu(h @ fc1_w^T + fc1_b) -> mlp [16384, 3072] fp16
    {
        dim3 grid(HIDDEN / 256, MROWS / 128);
        hgemm_nt<1,__half><<<grid, 256, HSM_BYTES>>>(h, wfc1, fc1_b,
                                                     nullptr, 0, mlp, HIDDEN,
                                                     CC, HIDDEN);
    }

    // 7) out = out + mlp @ fc2_w^T + fc2_b (fp32)
    {
        dim3 grid(CC / 256, MROWS / 128);
        hgemm_nt<2,float><<<grid, 256, HSM_BYTES>>>(mlp, wfc2, fc2_b,
                                                    out, CC, out, CC,
                                                    HIDDEN, CC);
    }
}

// round 17
// speedup vs baseline: 1.0428x; 1.0428x over previous
#include <cuda_runtime.h>
#include <cuda_fp16.h>
#include <cstdint>
#include <math.h>

// Problem constants
#define BQ      4
#define NT      4096
#define CC      768
#define NHEADS  12
#define NPTS    4
#define HDIM    64
#define HIDDEN  3072
#define MROWS   (BQ*NT)          // 16384
#define SCALE_ATTN 0.125f        // 64^-0.5
#define QKVW    (3*CC)           // 2304
#define QX      2560             // qkv + 96 offset cols, padded to 256
#define NOFF    96

// ---------------- scratch (device globals; no cudaMalloc allowed) ----------
__device__ __half g_h[(size_t)MROWS * CC];          // ln out (fp16 GEMM A)
__device__ float  g_qkvx[(size_t)MROWS * QX];       // qkv + offsets fused (fp32)
__device__ __half g_attn[(size_t)MROWS * CC];       // attention output (fp16)
__device__ __half g_mlp[(size_t)MROWS * HIDDEN];    // gelu(fc1) (fp16)
// fp16 weight copies (prepared once per launch)
__device__ __half g_wqkvx[(size_t)QX * CC];         // qkv_w ++ Weff ++ zero pad
__device__ float  g_biasx[QX];                      // qkv_b ++ beff ++ 0
__device__ __half g_wproj[(size_t)CC * CC];
__device__ __half g_wfc1[(size_t)HIDDEN * CC];
__device__ __half g_wfc2[(size_t)CC * HIDDEN];

// ---------------- weight prep: all four fp32->fp16 conversions in one ------
#define WN0 (QKVW*CC/4)      // 442368
#define WN1 (CC*CC/4)        // 147456
#define WN2 (HIDDEN*CC/4)    // 589824
#define WN3 (CC*HIDDEN/4)    // 589824
#define WNT (WN0+WN1+WN2+WN3)

__global__ __launch_bounds__(256) void wconv_all_kernel(
    const float* __restrict__ s0, __half* __restrict__ d0,
    const float* __restrict__ s1, __half* __restrict__ d1,
    const float* __restrict__ s2, __half* __restrict__ d2,
    const float* __restrict__ s3, __half* __restrict__ d3)
{
    int i = blockIdx.x * 256 + threadIdx.x;
    if (i >= WNT) return;
    const float* s; __half* d; int j = i;
    if (j < WN0)            { s = s0; d = d0; }
    else if ((j -= WN0) < WN1) { s = s1; d = d1; }
    else if ((j -= WN1) < WN2) { s = s2; d = d2; }
    else                    { j -= WN2; s = s3; d = d3; }
    float4 v = ((const float4*)s)[j];
    __half2 h0 = __floats2half2_rn(v.x, v.y);
    __half2 h1 = __floats2half2_rn(v.z, v.w);
    ((uint2*)d)[j] = make_uint2(*(uint32_t*)&h0, *(uint32_t*)&h1);
}

// Merged: Weff compose rows (grid.x < NOFF*3), bias vector, zero-pad rows.
// grid: (NOFF*3 + 1 + ZPAD_BLOCKS, 1); block 256.
#define ZPB ((QX - QKVW - NOFF) * CC / 256)   // zero-pad blocks: 160*768/256 = 480
__global__ __launch_bounds__(256) void wprep2_kernel(
    const float* __restrict__ qkv_w, const float* __restrict__ off_w,
    const float* __restrict__ qkv_b, const float* __restrict__ off_b,
    __half* __restrict__ wqkvx, float* __restrict__ biasx)
{
    int blk = blockIdx.x;
    if (blk < NOFF * 3) {
        // Weff[n][j] = sum_k off_w[n][k] * qkv_w[k][j]
        int n = blk / 3;
        int j = (blk % 3) * 256 + threadIdx.x;
        float s = 0.f;
        for (int k = 0; k < CC; k++)
            s = fmaf(__ldg(&off_w[n * CC + k]), qkv_w[(size_t)k * CC + j], s);
        wqkvx[(size_t)(QKVW + n) * CC + j] = __float2half_rn(s);
    } else if (blk < NOFF * 3 + (QX + 255) / 256) {
        // bias vector
        int i = (blk - NOFF * 3) * 256 + threadIdx.x;
        if (i < QX) {
            if (i < QKVW) biasx[i] = qkv_b[i];
            else if (i < QKVW + NOFF) {
                int n = i - QKVW;
                float s = off_b[n];
                for (int k = 0; k < CC; k++)
                    s = fmaf(off_w[n * CC + k], qkv_b[k], s);
                biasx[i] = s;
            } else biasx[i] = 0.f;
        }
    } else {
        // zero-pad rows QKVW+NOFF .. QX-1
        int z = (blk - NOFF * 3 - (QX + 255) / 256) * 256 + threadIdx.x;
        if (z < (QX - QKVW - NOFF) * CC)
            wqkvx[(size_t)(QKVW + NOFF) * CC + z] = __float2half_rn(0.f);
    }
}

// ---------------- LayerNorm: warp-per-row, 8 rows/block ---------------------
__global__ __launch_bounds__(256) void layernorm_kernel(
    const float* __restrict__ x, const float* __restrict__ w,
    const float* __restrict__ b, __half* __restrict__ out)
{
    int warp = threadIdx.x >> 5, lane = threadIdx.x & 31;
    int row = blockIdx.x * 8 + warp;
    const float* xr = x + (size_t)row * CC;

    float4 v[6];
    float s = 0.f, sq = 0.f;
    #pragma unroll
    for (int i = 0; i < 6; i++) {
        v[i] = ((const float4*)xr)[lane + i * 32];
        s  += v[i].x + v[i].y + v[i].z + v[i].w;
        sq += v[i].x*v[i].x + v[i].y*v[i].y + v[i].z*v[i].z + v[i].w*v[i].w;
    }
    #pragma unroll
    for (int o = 16; o > 0; o >>= 1) {
        s  += __shfl_xor_sync(0xffffffffu, s,  o);
        sq += __shfl_xor_sync(0xffffffffu, sq, o);
    }
    float mean = s * (1.0f / CC);
    float var  = sq * (1.0f / CC) - mean * mean;
    float rstd = rsqrtf(var + 1e-5f);

    __half* orow = out + (size_t)row * CC;
    #pragma unroll
    for (int i = 0; i < 6; i++) {
        int i4 = lane + i * 32;
        float4 wv = ((const float4*)w)[i4];
        float4 bv = ((const float4*)b)[i4];
        float r0 = (v[i].x - mean) * rstd * wv.x + bv.x;
        float r1 = (v[i].y - mean) * rstd * wv.y + bv.y;
        float r2 = (v[i].z - mean) * rstd * wv.z + bv.z;
        float r3 = (v[i].w - mean) * rstd * wv.w + bv.w;
        __half2 h01 = __floats2half2_rn(r0, r1);
        __half2 h23 = __floats2half2_rn(r2, r3);
        ((uint2*)orow)[i4] = make_uint2(*(uint32_t*)&h01, *(uint32_t*)&h23);
    }
}

// ============================================================================
// FP16 mma.sync GEMM: C[M,N] = A[M,K] * W[N,K]^T + bias (+epilogue)
// Block tile 128x256x32, 256 threads, warp tile 64x64, mma.m16n8k16,
// 3-stage cp.async.  (R12 proven config — GEMM pipe saturated, do not touch.)
// EPI: 0 = bias, 1 = bias + exact GELU, 2 = bias + residual add
// ============================================================================
#define HSTR 40        // smem row stride in halves (32 + 8 pad)
#define STG_H 15360    // halves per stage: A 128*40 + B 256*40
#define HSM_BYTES (3 * STG_H * 2)   // 92160

__device__ __forceinline__ void cp_async16(void* smem_dst, const void* gmem_src) {
    uint32_t s = (uint32_t)__cvta_generic_to_shared(smem_dst);
    asm volatile("cp.async.cg.shared.global [%0], [%1], 16;\n" :: "r"(s), "l"(gmem_src));
}

template<int EPI, typename OutT>
__global__ __launch_bounds__(256) void hgemm_nt(
    const __half* __restrict__ A,           // [M, K], lda == K
    const __half* __restrict__ Bw,          // [N', K], K contiguous
    const float* __restrict__ bias,
    const float* __restrict__ Res, int ldr,
    OutT* __restrict__ C, int ldc,
    int K, int nvalid)
{
    extern __shared__ __half smh[];

    const int t = threadIdx.x;
    const int rowTile = blockIdx.y * 128;
    const int colTile = blockIdx.x * 256;

    const int warp = t >> 5, lane = t & 31;
    const int wm = (warp & 1) * 64;        // 2 warps along M
    const int wn = (warp >> 1) * 64;       // 4 warps along N
    const int g  = lane >> 2;              // 0..7
    const int t4 = lane & 3;               // 0..3

    float acc[4][8][4];
    #pragma unroll
    for (int i = 0; i < 4; i++)
        #pragma unroll
        for (int j = 0; j < 8; j++)
            #pragma unroll
            for (int r = 0; r < 4; r++) acc[i][j][r] = 0.f;

    const int NK = K / 32;

    auto load_tile = [&](int kt, int buf) {
        const int kk = kt * 32;
        __half* As = smh + buf * STG_H;
        __half* Bs = As + 128 * HSTR;
        #pragma unroll
        for (int i = 0; i < 2; i++) {
            int c = t + i * 256;
            int row = c >> 2, kc = (c & 3) * 8;
            cp_async16(&As[row * HSTR + kc],
                       A + (size_t)(rowTile + row) * K + kk + kc);
        }
        #pragma unroll
        for (int i = 0; i < 4; i++) {
            int c = t + i * 256;
            int row = c >> 2, kc = (c & 3) * 8;
            cp_async16(&Bs[row * HSTR + kc],
                       Bw + (size_t)(colTile + row) * K + kk + kc);
        }
        asm volatile("cp.async.commit_group;\n");
    };

    load_tile(0, 0);
    if (NK > 1) load_tile(1, 1);

    for (int kt = 0; kt < NK; kt++) {
        const int buf = kt % 3;
        if (kt + 1 < NK) asm volatile("cp.async.wait_group 1;\n");
        else             asm volatile("cp.async.wait_group 0;\n");
        __syncthreads();

        const __half* As = smh + buf * STG_H;
        const __half* Bs = As + 128 * HSTR;

        #pragma unroll
        for (int ks = 0; ks < 2; ks++) {
            const int k0 = ks * 16;
            uint32_t afr[4][4];
            #pragma unroll
            for (int i = 0; i < 4; i++) {
                int rr = wm + i * 16 + g;
                afr[i][0] = *(const uint32_t*)&As[(rr    ) * HSTR + k0 + 2 * t4];
                afr[i][1] = *(const uint32_t*)&As[(rr + 8) * HSTR + k0 + 2 * t4];
                afr[i][2] = *(const uint32_t*)&As[(rr    ) * HSTR + k0 + 2 * t4 + 8];
                afr[i][3] = *(const uint32_t*)&As[(rr + 8) * HSTR + k0 + 2 * t4 + 8];
            }
            uint32_t bfr[8][2];
            #pragma unroll
            for (int j = 0; j < 8; j++) {
                int cc = wn + j * 8 + g;
                bfr[j][0] = *(const uint32_t*)&Bs[cc * HSTR + k0 + 2 * t4];
                bfr[j][1] = *(const uint32_t*)&Bs[cc * HSTR + k0 + 2 * t4 + 8];
            }
            #pragma unroll
            for (int i = 0; i < 4; i++)
                #pragma unroll
                for (int j = 0; j < 8; j++) {
                    asm volatile(
                        "mma.sync.aligned.m16n8k16.row.col.f32.f16.f16.f32 "
                        "{%0,%1,%2,%3}, {%4,%5,%6,%7}, {%8,%9}, {%0,%1,%2,%3};\n"
                        : "+f"(acc[i][j][0]), "+f"(acc[i][j][1]),
                          "+f"(acc[i][j][2]), "+f"(acc[i][j][3])
                        : "r"(afr[i][0]), "r"(afr[i][1]), "r"(afr[i][2]), "r"(afr[i][3]),
                          "r"(bfr[j][0]), "r"(bfr[j][1]));
                }
        }

        if (kt + 2 < NK) load_tile(kt + 2, (kt + 2) % 3);
    }

    // epilogue: acc[i][j] -> rows {wm+i*16+g, +8}, cols {wn+j*8+2*t4, +1}
    #pragma unroll
    for (int i = 0; i < 4; i++) {
        #pragma unroll
        for (int half = 0; half < 2; half++) {
            int r = rowTile + wm + i * 16 + g + half * 8;
            OutT* crow = C + (size_t)r * ldc;
            const float* rrow = (EPI == 2) ? (Res + (size_t)r * ldr) : nullptr;
            #pragma unroll
            for (int j = 0; j < 8; j++) {
                int cg = colTile + wn + j * 8 + t4 * 2;
                if (cg >= nvalid) continue;
                float v0 = acc[i][j][half * 2 + 0] + bias[cg];
                float v1 = acc[i][j][half * 2 + 1] + bias[cg + 1];
                if (EPI == 1) {
                    v0 = 0.5f * v0 * (1.0f + erff(v0 * 0.70710678118654752f));
                    v1 = 0.5f * v1 * (1.0f + erff(v1 * 0.70710678118654752f));
                }
                if (EPI == 2) { v0 += rrow[cg]; v1 += rrow[cg + 1]; }
                if (sizeof(OutT) == 2) {
                    __half2 hv = __floats2half2_rn(v0, v1);
                    *(__half2*)((__half*)crow + cg) = hv;
                } else {
                    *(float2*)((float*)crow + cg) = make_float2(v0, v1);
                }
            }
        }
    }
}

// ---------------- deformable sampling + attention --------------------------
// One token per 192-thread block (R15-proven). Warp = 2 heads:
// half-warp (16 lanes x float4 = 64 channels) per head.
__global__ __launch_bounds__(192) void attn_kernel(
    const float* __restrict__ qkvx,   // [M, QX] fp32 (qkv ++ offsets)
    const float* __restrict__ refp,   // [M, 2]
    __half* __restrict__ out,         // [M, 768] fp16
    const int* __restrict__ Hp, const int* __restrict__ Wp)
{
    int bn   = blockIdx.x;
    int warp = threadIdx.x >> 5;
    int lane = threadIdx.x & 31;
    int hsel = lane >> 4;             // 0/1: which head in this warp
    int hlane = lane & 15;            // lane within head (owns 4 channels)
    int head = warp * 2 + hsel;
    int b = bn / NT;

    int H = *Hp, W = *Wp;
    float fW = (float)W, fH = (float)H;

    const float* rowq = qkvx + (size_t)bn * QX;
    float4 q = ((const float4*)(rowq + head * HDIM))[hlane];

    float ref0 = refp[(size_t)bn * 2 + 0];
    float ref1 = refp[(size_t)bn * 2 + 1];

    const float* offp = rowq + QKVW + head * (NPTS * 2);

    float dots[NPTS];
    float4 sv[NPTS];

    #pragma unroll
    for (int p = 0; p < NPTS; p++) {
        float o0 = offp[p * 2 + 0];
        float o1 = offp[p * 2 + 1];
        float gx = 2.0f * (ref0 + o0 / fW) - 1.0f;
        float gy = 2.0f * (ref1 + o1 / fH) - 1.0f;
        float x = ((gx + 1.0f) * fW - 1.0f) * 0.5f;
        float y = ((gy + 1.0f) * fH - 1.0f) * 0.5f;
        float x0f = floorf(x), y0f = floorf(y);
        float wx = x - x0f, wy = y - y0f;
        int x0 = (int)x0f, y0 = (int)y0f;

        float cw[4] = {(1.f - wx) * (1.f - wy), wx * (1.f - wy),
                       (1.f - wx) * wy,          wx * wy};
        int cx[4] = {x0, x0 + 1, x0,     x0 + 1};
        int cy[4] = {y0, y0,     y0 + 1, y0 + 1};

        float4 sk = make_float4(0.f, 0.f, 0.f, 0.f);
        float4 vv = make_float4(0.f, 0.f, 0.f, 0.f);
        #pragma unroll
        for (int c = 0; c < 4; c++) {
            int ix = cx[c], iy = cy[c];
            if (ix >= 0 && ix < W && iy >= 0 && iy < H) {
                const float* rowk = qkvx + (size_t)(b * NT + iy * W + ix) * QX
                                  + head * HDIM;
                float4 k4 = ((const float4*)(rowk + CC))[hlane];
                float4 v4 = ((const float4*)(rowk + 2 * CC))[hlane];
                float w = cw[c];
                sk.x = fmaf(w, k4.x, sk.x); sk.y = fmaf(w, k4.y, sk.y);
                sk.z = fmaf(w, k4.z, sk.z); sk.w = fmaf(w, k4.w, sk.w);
                vv.x = fmaf(w, v4.x, vv.x); vv.y = fmaf(w, v4.y, vv.y);
                vv.z = fmaf(w, v4.z, vv.z); vv.w = fmaf(w, v4.w, vv.w);
            }
        }
        sv[p] = vv;

        float dot = q.x * sk.x + q.y * sk.y + q.z * sk.z + q.w * sk.w;
        #pragma unroll
        for (int o = 8; o > 0; o >>= 1)
            dot += __shfl_xor_sync(0xffffffffu, dot, o);   // 16-lane reduce
        dots[p] = dot * SCALE_ATTN;
    }

    float mx = fmaxf(fmaxf(dots[0], dots[1]), fmaxf(dots[2], dots[3]));
    float e[NPTS], es = 0.f;
    #pragma unroll
    for (int p = 0; p < NPTS; p++) { e[p] = __expf(dots[p] - mx); es += e[p]; }
    float inv = 1.0f / es;

    float4 o4 = make_float4(0.f, 0.f, 0.f, 0.f);
    #pragma unroll
    for (int p = 0; p < NPTS; p++) {
        float a = e[p] * inv;
        o4.x = fmaf(a, sv[p].x, o4.x); o4.y = fmaf(a, sv[p].y, o4.y);
        o4.z = fmaf(a, sv[p].z, o4.z); o4.w = fmaf(a, sv[p].w, o4.w);
    }
    __half2 h01 = __floats2half2_rn(o4.x, o4.y);
    __half2 h23 = __floats2half2_rn(o4.z, o4.w);
    *(uint2*)(out + (size_t)bn * CC + head * HDIM + hlane * 4)
        = make_uint2(*(uint32_t*)&h01, *(uint32_t*)&h23);
}

// ---------------- launch ----------------------------------------------------
extern "C" void kernel_launch(void* const* d_in, const int* in_sizes, int n_in,
                              void* d_out, int out_size)
{
    const float* x      = (const float*)d_in[0];
    const float* refp   = (const float*)d_in[1];
    const float* n1w    = (const float*)d_in[2];
    const float* n1b    = (const float*)d_in[3];
    const float* qkv_w  = (const float*)d_in[4];
    const float* qkv_b  = (const float*)d_in[5];
    const float* off_w  = (const float*)d_in[6];
    const float* off_b  = (const float*)d_in[7];
    const float* proj_w = (const float*)d_in[8];
    const float* proj_b = (const float*)d_in[9];
    const float* n2w    = (const float*)d_in[10];
    const float* n2b    = (const float*)d_in[11];
    const float* fc1_w  = (const float*)d_in[12];
    const float* fc1_b  = (const float*)d_in[13];
    const float* fc2_w  = (const float*)d_in[14];
    const float* fc2_b  = (const float*)d_in[15];
    const int*   Hp     = (const int*)d_in[16];
    const int*   Wp     = (const int*)d_in[17];
    float* out = (float*)d_out;

    __half* h     = nullptr; cudaGetSymbolAddress((void**)&h,     g_h);
    float*  qkvx  = nullptr; cudaGetSymbolAddress((void**)&qkvx,  g_qkvx);
    __half* attn  = nullptr; cudaGetSymbolAddress((void**)&attn,  g_attn);
    __half* mlp   = nullptr; cudaGetSymbolAddress((void**)&mlp,   g_mlp);
    __half* wqkvx = nullptr; cudaGetSymbolAddress((void**)&wqkvx, g_wqkvx);
    float*  biasx = nullptr; cudaGetSymbolAddress((void**)&biasx, g_biasx);
    __half* wproj = nullptr; cudaGetSymbolAddress((void**)&wproj, g_wproj);
    __half* wfc1  = nullptr; cudaGetSymbolAddress((void**)&wfc1,  g_wfc1);
    __half* wfc2  = nullptr; cudaGetSymbolAddress((void**)&wfc2,  g_wfc2);

    static bool attr_done = false;
    if (!attr_done) {
        cudaFuncSetAttribute((const void*)hgemm_nt<0,float>,  cudaFuncAttributeMaxDynamicSharedMemorySize, HSM_BYTES);
        cudaFuncSetAttribute((const void*)hgemm_nt<1,__half>, cudaFuncAttributeMaxDynamicSharedMemorySize, HSM_BYTES);
        cudaFuncSetAttribute((const void*)hgemm_nt<2,float>,  cudaFuncAttributeMaxDynamicSharedMemorySize, HSM_BYTES);
        attr_done = true;
    }

    // 0) weight prep: one conversion kernel + one compose/bias/pad kernel
    wconv_all_kernel<<<(WNT + 255) / 256, 256>>>(qkv_w, wqkvx, proj_w, wproj,
                                                 fc1_w, wfc1, fc2_w, wfc2);
    wprep2_kernel<<<NOFF * 3 + (QX + 255) / 256 + ZPB, 256>>>(
        qkv_w, off_w, qkv_b, off_b, wqkvx, biasx);

    // 1) ln1: x -> h (fp16)
    layernorm_kernel<<<MROWS / 8, 256>>>(x, n1w, n1b, h);

    // 2) qkvx = h @ [qkv_w;Weff]^T + bias : [16384, QX] fp32 (valid 2400)
    {
        dim3 grid(QX / 256, MROWS / 128);
        hgemm_nt<0,float><<<grid, 256, HSM_BYTES>>>(h, wqkvx, biasx,
                                                    nullptr, 0, qkvx, QX,
                                                    CC, QKVW + NOFF);
    }

    // 3) deformable sampling + attention -> attn [16384, 768] fp16
    attn_kernel<<<BQ * NT, 192>>>(qkvx, refp, attn, Hp, Wp);

    // 4) x1 = x + attn @ proj_w^T + proj_b -> out (fp32)
    {
        dim3 grid(CC / 256, MROWS / 128);
        hgemm_nt<2,float><<<grid, 256, HSM_BYTES>>>(attn, wproj, proj_b,
                                                    x, CC, out, CC, CC, CC);
    }

    // 5) ln2: out -> h (fp16)
    layernorm_kernel<<<MROWS / 8, 256>>>(out, n2w, n2b, h);

    // 6) m = gelu(h @ fc1_w^T + fc1_b) -> mlp [16384, 3072] fp16
    {
        dim3 grid(HIDDEN / 256, MROWS / 128);
        hgemm_nt<1,__half><<<grid, 256, HSM_BYTES>>>(h, wfc1, fc1_b,
                                                     nullptr, 0, mlp, HIDDEN,
                                                     CC, HIDDEN);
    }

    // 7) out = out + mlp @ fc2_w^T + fc2_b (fp32)
    {
        dim3 grid(CC / 256, MROWS / 128);
        hgemm_nt<2,float><<<grid, 256, HSM_BYTES>>>(mlp, wfc2, fc2_b,
                                                    out, CC, out, CC,
                                                    HIDDEN, CC);
    }
}